// round 5
// baseline (speedup 1.0000x reference)
#include <cuda_runtime.h>
#include <cuda_bf16.h>

#define HW      65536
#define WMASK   255
#define NROWS   600
#define NPAD    640
#define TT      60
#define NT      64
#define CLS     91
#define KSLICES 32
#define KSPAN   2048
#define KSTEPS  (KSPAN/16)   // 128
#define MTILES  10

// ---------------- scratch (static, no allocation) ----------------
__device__ float g_partP[KSLICES*NPAD*NT];   // per-kslice partial p.t^T
__device__ float g_partD[KSLICES*NPAD*NT];   // per-kslice partial (pos-neg).t^T
__device__ float g_partNS[KSLICES*NPAD];     // per-kslice partial sum(neg)
__device__ float g_accP[NPAD*NT];
__device__ float g_accD[NPAD*NT];
__device__ float g_negsum[NPAD];
__device__ unsigned g_pmm[NPAD*4];           // 0:xmin 1:ymin (min), 2:xmax 3:ymax (max) — monotone-uint
__device__ __align__(16) unsigned g_bfrag[4096*32*16];  // B in mma fragment order, 8MB
__device__ float g_tsum[NT];
__device__ float g_tbox[NT*4];               // tgt masks_to_boxes xyxy

// monotone float<->orderable-uint
__device__ __forceinline__ unsigned f2o(float f){
  unsigned u = __float_as_uint(f);
  return (u & 0x80000000u) ? ~u : (u | 0x80000000u);
}
__device__ __forceinline__ float o2f(unsigned u){
  return __uint_as_float((u & 0x80000000u) ? (u & 0x7FFFFFFFu) : ~u);
}

__device__ __forceinline__ unsigned pack2(float a, float b){
  __nv_bfloat162 h = __floats2bfloat162_rn(a, b);
  return *reinterpret_cast<unsigned*>(&h);
}

__device__ __forceinline__ void mma16816(float* c, unsigned a0,unsigned a1,unsigned a2,unsigned a3,
                                         unsigned b0, unsigned b1){
  asm volatile("mma.sync.aligned.m16n8k16.row.col.f32.bf16.bf16.f32 "
    "{%0,%1,%2,%3}, {%4,%5,%6,%7}, {%8,%9}, {%0,%1,%2,%3};\n"
    : "+f"(c[0]), "+f"(c[1]), "+f"(c[2]), "+f"(c[3])
    : "r"(a0), "r"(a1), "r"(a2), "r"(a3), "r"(b0), "r"(b1));
}

// ---------------- init ----------------
__global__ void k_zero(){
  int i = blockIdx.x*256 + threadIdx.x;
  if (i < NPAD*4) g_pmm[i] = ((i&3) < 2) ? 0xFFFFFFFFu : 0u;
}

// ---------------- build B fragments (targets, bf16, mma layout) ----------------
__global__ void k_bfrag(const int* __restrict__ tm){
  __shared__ unsigned short Bt[64][16];  // [n][k] bf16 bits
  const int s   = blockIdx.x;            // global k-step (0..4095)
  const int tid = threadIdx.x;
  for (int e = tid; e < 64*16; e += 256){
    int ki = e & 15, n = e >> 4;
    float v;
    if (n < TT)      v = (float)tm[n*HW + s*16 + ki];
    else if (n == TT) v = 1.0f;          // ones column -> row sums of p
    else             v = 0.0f;
    Bt[n][ki] = __bfloat16_as_ushort(__float2bfloat16(v));
  }
  __syncthreads();
  const int l = tid >> 3, t = tid & 7;
  const int tig = l & 3, g = l >> 2;
  const int n = t*8 + g;
  unsigned r0 = *(const unsigned*)&Bt[n][tig*2];      // k = 2*tig, 2*tig+1
  unsigned r1 = *(const unsigned*)&Bt[n][tig*2 + 8];  // k = 2*tig+8, +9
  unsigned base = (unsigned)(s*32 + l)*16 + t*2;
  g_bfrag[base]   = r0;
  g_bfrag[base+1] = r1;
}

// ---------------- target stats: row sums + masks_to_boxes ----------------
__global__ void k_tstats(const int* __restrict__ tm){
  const int j = blockIdx.x;
  const int tid = threadIdx.x;
  float cnt = 0.f, xmn = 1e8f, ymn = 1e8f, xmx = 0.f, ymx = 0.f;
  for (int px = tid; px < HW; px += 256){
    int m = tm[j*HW + px];
    if (m){
      float xc = (float)(px & WMASK), yc = (float)(px >> 8);
      cnt += 1.f;
      xmn = fminf(xmn, xc); ymn = fminf(ymn, yc);
      xmx = fmaxf(xmx, xc); ymx = fmaxf(ymx, yc);
    }
  }
  __shared__ float sb[256];
  sb[tid] = cnt; __syncthreads();
  for (int o=128;o>0;o>>=1){ if (tid<o) sb[tid]+=sb[tid+o]; __syncthreads(); }
  if (tid==0) g_tsum[j] = sb[0];
  __syncthreads();
  sb[tid] = xmn; __syncthreads();
  for (int o=128;o>0;o>>=1){ if (tid<o) sb[tid]=fminf(sb[tid],sb[tid+o]); __syncthreads(); }
  if (tid==0) g_tbox[j*4+0] = sb[0];
  __syncthreads();
  sb[tid] = ymn; __syncthreads();
  for (int o=128;o>0;o>>=1){ if (tid<o) sb[tid]=fminf(sb[tid],sb[tid+o]); __syncthreads(); }
  if (tid==0) g_tbox[j*4+1] = sb[0];
  __syncthreads();
  sb[tid] = xmx; __syncthreads();
  for (int o=128;o>0;o>>=1){ if (tid<o) sb[tid]=fmaxf(sb[tid],sb[tid+o]); __syncthreads(); }
  if (tid==0) g_tbox[j*4+2] = sb[0];
  __syncthreads();
  sb[tid] = ymx; __syncthreads();
  for (int o=128;o>0;o>>=1){ if (tid<o) sb[tid]=fmaxf(sb[tid],sb[tid+o]); __syncthreads(); }
  if (tid==0) g_tbox[j*4+3] = sb[0];
}

// ---------------- main: sigmoid/focal transform + tensor-core dots + fused box min/max ----------------
// per float2: p = sigmoid(x); -log p = log1p(e^-x); -log(1-p) = x + log1p(e^-x)
#define TF2(xv, cidx, pr, dr, nsacc, XMX, XMN, YMX, YMN) {                      \
  float x0_ = (xv).x, x1_ = (xv).y;                                             \
  float e0_ = __expf(-x0_), e1_ = __expf(-x1_);                                 \
  float P0_ = __fdividef(1.f, 1.f+e0_), P1_ = __fdividef(1.f, 1.f+e1_);         \
  float S0_ = __logf(1.f+e0_), S1_ = __logf(1.f+e1_);                           \
  float n0_ = 0.75f*P0_*P0_*(x0_+S0_), n1_ = 0.75f*P1_*P1_*(x1_+S1_);           \
  float o0_ = 1.f-P0_, o1_ = 1.f-P1_;                                           \
  float D0_ = 0.25f*o0_*o0_*S0_ - n0_, D1_ = 0.25f*o1_*o1_*S1_ - n1_;           \
  nsacc += n0_ + n1_;                                                           \
  { float xc0_ = (float)((cidx)&WMASK),     yc0_ = (float)((cidx)>>8);          \
    float xc1_ = (float)(((cidx)+1)&WMASK), yc1_ = (float)(((cidx)+1)>>8);      \
    float a_ = x0_*xc0_, b_ = x0_*yc0_, c_ = x1_*xc1_, d2_ = x1_*yc1_;          \
    XMX = fmaxf(XMX, fmaxf(a_, c_));                                            \
    YMX = fmaxf(YMX, fmaxf(b_, d2_));                                           \
    XMN = fminf(XMN, fminf(x0_!=0.f?a_:1e8f,  x1_!=0.f?c_:1e8f));               \
    YMN = fminf(YMN, fminf(x0_!=0.f?b_:1e8f,  x1_!=0.f?d2_:1e8f)); }            \
  pr = pack2(P0_, P1_); dr = pack2(D0_, D1_); }

#define QSUM(v) { v += __shfl_down_sync(0xffffffffu, v, 2); v += __shfl_down_sync(0xffffffffu, v, 1); }
#define QMAX(v) { v = fmaxf(v, __shfl_down_sync(0xffffffffu, v, 2)); v = fmaxf(v, __shfl_down_sync(0xffffffffu, v, 1)); }
#define QMIN(v) { v = fminf(v, __shfl_down_sync(0xffffffffu, v, 2)); v = fminf(v, __shfl_down_sync(0xffffffffu, v, 1)); }

__global__ void __launch_bounds__(128) k_main(const float* __restrict__ pm){
  const int kslice = blockIdx.x;     // 0..31
  const int mtile  = blockIdx.y;     // 0..9
  const int warp = threadIdx.x >> 5;
  const int lane = threadIdx.x & 31;
  const int tig  = lane & 3;
  const int g    = lane >> 2;
  const int row_lo = mtile*64 + warp*16 + g;
  const int row_hi = row_lo + 8;
  const bool vlo = row_lo < NROWS;
  const bool vhi = row_hi < NROWS;
  const float* Alo = pm + (size_t)row_lo * HW;
  const float* Ahi = pm + (size_t)row_hi * HW;

  float aP[32], aD[32];
#pragma unroll
  for (int i=0;i<32;i++){ aP[i]=0.f; aD[i]=0.f; }
  float ns_lo=0.f, ns_hi=0.f;
  float xmx_lo=-3e38f, ymx_lo=-3e38f, xmn_lo=3e38f, ymn_lo=3e38f;
  float xmx_hi=-3e38f, ymx_hi=-3e38f, xmn_hi=3e38f, ymn_hi=3e38f;

  const unsigned* bbase = g_bfrag + (size_t)((kslice*KSTEPS)*32 + lane)*16;

#pragma unroll 1
  for (int ks = 0; ks < KSTEPS; ks++){
    const int c0 = kslice*KSPAN + ks*16 + tig*2;
    const int c8 = c0 + 8;
    float2 z = make_float2(0.f, 0.f);
    float2 xl0 = vlo ? *(const float2*)(Alo + c0) : z;
    float2 xh0 = vhi ? *(const float2*)(Ahi + c0) : z;
    float2 xl8 = vlo ? *(const float2*)(Alo + c8) : z;
    float2 xh8 = vhi ? *(const float2*)(Ahi + c8) : z;

    const uint4* bp = (const uint4*)(bbase + (size_t)ks*32*16);
    uint4 q0 = bp[0], q1 = bp[1], q2 = bp[2], q3 = bp[3];
    unsigned B[16] = {q0.x,q0.y,q0.z,q0.w, q1.x,q1.y,q1.z,q1.w,
                      q2.x,q2.y,q2.z,q2.w, q3.x,q3.y,q3.z,q3.w};

    unsigned ap0,ad0,ap1,ad1,ap2,ad2,ap3,ad3;
    TF2(xl0, c0, ap0, ad0, ns_lo, xmx_lo, xmn_lo, ymx_lo, ymn_lo);
    TF2(xh0, c0, ap1, ad1, ns_hi, xmx_hi, xmn_hi, ymx_hi, ymn_hi);
    TF2(xl8, c8, ap2, ad2, ns_lo, xmx_lo, xmn_lo, ymx_lo, ymn_lo);
    TF2(xh8, c8, ap3, ad3, ns_hi, xmx_hi, xmn_hi, ymx_hi, ymn_hi);

#pragma unroll
    for (int t=0;t<8;t++){
      mma16816(aP + t*4, ap0, ap1, ap2, ap3, B[2*t], B[2*t+1]);
      mma16816(aD + t*4, ad0, ad1, ad2, ad3, B[2*t], B[2*t+1]);
    }
  }

  // write per-slice partials (unique writer per element -> deterministic)
  float* PP = g_partP + (size_t)kslice*NPAD*NT;
  float* PD = g_partD + (size_t)kslice*NPAD*NT;
#pragma unroll
  for (int t=0;t<8;t++){
    int cb = t*8 + tig*2;
    PP[row_lo*NT + cb]   = aP[t*4+0];
    PP[row_lo*NT + cb+1] = aP[t*4+1];
    PP[row_hi*NT + cb]   = aP[t*4+2];
    PP[row_hi*NT + cb+1] = aP[t*4+3];
    PD[row_lo*NT + cb]   = aD[t*4+0];
    PD[row_lo*NT + cb+1] = aD[t*4+1];
    PD[row_hi*NT + cb]   = aD[t*4+2];
    PD[row_hi*NT + cb+1] = aD[t*4+3];
  }

  QSUM(ns_lo); QSUM(ns_hi);
  QMAX(xmx_lo); QMAX(ymx_lo); QMIN(xmn_lo); QMIN(ymn_lo);
  QMAX(xmx_hi); QMAX(ymx_hi); QMIN(xmn_hi); QMIN(ymn_hi);
  if (tig == 0){
    g_partNS[kslice*NPAD + row_lo] = ns_lo;
    g_partNS[kslice*NPAD + row_hi] = ns_hi;
    atomicMin(&g_pmm[row_lo*4+0], f2o(xmn_lo));
    atomicMin(&g_pmm[row_lo*4+1], f2o(ymn_lo));
    atomicMax(&g_pmm[row_lo*4+2], f2o(xmx_lo));
    atomicMax(&g_pmm[row_lo*4+3], f2o(ymx_lo));
    atomicMin(&g_pmm[row_hi*4+0], f2o(xmn_hi));
    atomicMin(&g_pmm[row_hi*4+1], f2o(ymn_hi));
    atomicMax(&g_pmm[row_hi*4+2], f2o(xmx_hi));
    atomicMax(&g_pmm[row_hi*4+3], f2o(ymx_hi));
  }
}

// ---------------- deterministic cross-slice reduction ----------------
__global__ void k_reduce(){
  int i = blockIdx.x*256 + threadIdx.x;
  if (i < NPAD*NT){
    float sp = 0.f, sd = 0.f;
#pragma unroll 1
    for (int s=0;s<KSLICES;s++){
      sp += g_partP[(size_t)s*NPAD*NT + i];
      sd += g_partD[(size_t)s*NPAD*NT + i];
    }
    g_accP[i] = sp; g_accD[i] = sd;
  }
  if (i < NPAD){
    float sn = 0.f;
#pragma unroll 1
    for (int s=0;s<KSLICES;s++) sn += g_partNS[s*NPAD + i];
    g_negsum[i] = sn;
  }
}

// ---------------- final cost assembly ----------------
__device__ __forceinline__ float giou_fn(float a0,float a1,float a2,float a3,
                                         float b0,float b1,float b2,float b3){
  float area1 = (a2-a0)*(a3-a1);
  float area2 = (b2-b0)*(b3-b1);
  float ltx = fmaxf(a0,b0), lty = fmaxf(a1,b1);
  float rbx = fminf(a2,b2), rby = fminf(a3,b3);
  float wx = fmaxf(rbx-ltx, 0.f), wy = fmaxf(rby-lty, 0.f);
  float inter = wx*wy;
  float uni = area1 + area2 - inter;
  float iou = inter / uni;
  float lex = fminf(a0,b0), ley = fminf(a1,b1);
  float rex = fmaxf(a2,b2), rey = fmaxf(a3,b3);
  float ewx = fmaxf(rex-lex, 0.f), ewy = fmaxf(rey-ley, 0.f);
  float ea = ewx*ewy;
  return iou - (ea - uni)/ea;
}

__global__ void k_final(const float* __restrict__ logits, const float* __restrict__ pboxes,
                        const float* __restrict__ tboxes, const int* __restrict__ tids,
                        float* __restrict__ out){
  const int i = blockIdx.x;
  const int j = threadIdx.x;
  if (j >= TT) return;

  float pcx = pboxes[i*4+0], pcy = pboxes[i*4+1], pw = pboxes[i*4+2], ph = pboxes[i*4+3];
  float p0 = pcx-0.5f*pw, p1 = pcy-0.5f*ph, p2 = pcx+0.5f*pw, p3 = pcy+0.5f*ph;

  // mask-derived pred box (xyxy) then cxcywh->xyxy (faithful to reference)
  float mx = o2f(g_pmm[i*4+0]), my = o2f(g_pmm[i*4+1]);
  float mw = o2f(g_pmm[i*4+2]), mh = o2f(g_pmm[i*4+3]);
  float q0 = mx-0.5f*mw, q1 = my-0.5f*mh, q2 = mx+0.5f*mw, q3 = my+0.5f*mh;

  float psum = g_accP[i*NT + TT];   // ones-column -> sum(p) per row
  float nsum = g_negsum[i];

  float tcx = tboxes[j*4+0], tcy = tboxes[j*4+1], tw = tboxes[j*4+2], th = tboxes[j*4+3];
  float t0 = tcx-0.5f*tw, t1 = tcy-0.5f*th, t2 = tcx+0.5f*tw, t3 = tcy+0.5f*th;

  float cost_bbox = fabsf(pcx-tcx)+fabsf(pcy-tcy)+fabsf(pw-tw)+fabsf(ph-th);
  float g1 = giou_fn(p0,p1,p2,p3, t0,t1,t2,t3);

  float ux = g_tbox[j*4+0], uy = g_tbox[j*4+1], uw = g_tbox[j*4+2], uh = g_tbox[j*4+3];
  float u0 = ux-0.5f*uw, u1 = uy-0.5f*uh, u2 = ux+0.5f*uw, u3 = uy+0.5f*uh;
  float g2 = giou_fn(q0,q1,q2,q3, u0,u1,u2,u3);

  int id = tids[j];
  float lg = logits[i*CLS + id];
  float pp = 1.f/(1.f + expf(-lg));
  float posc = 0.25f*(1.f-pp)*(1.f-pp)*(-logf(pp + 1e-8f));
  float negc = 0.75f*pp*pp*(-logf(1.f-pp + 1e-8f));
  float cclass = posc - negc;

  float inter = g_accP[i*NT + j];
  float dice  = 1.f - (2.f*inter + 1e-5f)/(psum + g_tsum[j] + 1e-5f);
  float dd    = g_accD[i*NT + j];
  float focal = (dd + nsum) * (1.0f/65536.0f);

  out[i*TT + j] = cost_bbox + cclass - g1 - g2 + dice + focal;
}

// ---------------- launch ----------------
extern "C" void kernel_launch(void* const* d_in, const int* in_sizes, int n_in,
                              void* d_out, int out_size){
  (void)in_sizes; (void)n_in; (void)out_size;
  const float* logits = (const float*)d_in[0];
  const float* pboxes = (const float*)d_in[1];
  const float* pmasks = (const float*)d_in[2];
  const float* tboxes = (const float*)d_in[3];
  const int*   tids   = (const int*)d_in[4];
  const int*   tmasks = (const int*)d_in[5];
  float* out = (float*)d_out;

  k_zero<<<(NPAD*4 + 255)/256, 256>>>();
  k_bfrag<<<4096, 256>>>(tmasks);
  k_tstats<<<TT, 256>>>(tmasks);
  k_main<<<dim3(KSLICES, MTILES), 128>>>(pmasks);
  k_reduce<<<(NPAD*NT + 255)/256, 256>>>();
  k_final<<<NROWS, 64>>>(logits, pboxes, tboxes, tids, out);
}